// round 1
// baseline (speedup 1.0000x reference)
#include <cuda_runtime.h>
#include <math.h>

// ---------------- Problem constants ----------------
#define BATCH 512
#define C1 256            // conv1 out channels
#define H1 20             // conv1 out spatial
#define ROUTES 1152
#define PCAPS 8
#define NCAPS 10
#define CAPDIM 16
#define M2 (BATCH*36)     // 18432
#define K2 (256*81)       // 20736
#define N2 256
#define FLAT 9216         // 256*36 per batch

// ---------------- Device scratch (no allocations allowed) ----------------
__device__ __align__(16) float g_x1[BATCH*C1*H1*H1];     // conv1 out  (210MB)
__device__ __align__(16) float g_wT[K2*N2];              // transposed pc_w (21MB)
__device__ __align__(16) float g_c2[BATCH*FLAT];         // conv2 out flat (19MB)
__device__ __align__(16) float g_u[BATCH*FLAT];          // squashed u
__device__ __align__(16) float g_uhat[BATCH*ROUTES*NCAPS*CAPDIM]; // 377MB
__device__ __align__(16) float g_bij[ROUTES*NCAPS];
__device__ __align__(16) float g_cij[ROUTES*NCAPS];
__device__ __align__(16) float g_v[BATCH*NCAPS*CAPDIM];
__device__ int   g_best[BATCH];
__device__ __align__(16) float g_h1[BATCH*512];
__device__ __align__(16) float g_h2[BATCH*1024];

// ---------------- Weight transpose: wT[k][n] = pc_w[n][k] ----------------
__global__ void transpose_w_kernel(const float* __restrict__ w, float* __restrict__ wT) {
    __shared__ float t[32][33];
    int k0 = blockIdx.x * 32, n0 = blockIdx.y * 32;
    int tx = threadIdx.x, ty = threadIdx.y;   // 32 x 8
    #pragma unroll
    for (int i = ty; i < 32; i += 8)
        t[i][tx] = w[(size_t)(n0 + i) * K2 + k0 + tx];
    __syncthreads();
    #pragma unroll
    for (int i = ty; i < 32; i += 8)
        wT[(size_t)(k0 + i) * N2 + n0 + tx] = t[tx][i];
}

// ---------------- Conv1: 1->256, 9x9, stride1, relu ----------------
__global__ void conv1_kernel(const float* __restrict__ img, const float* __restrict__ w,
                             const float* __restrict__ bias, float* __restrict__ x1) {
    __shared__ float ism[784];
    __shared__ float wsm[32 * 81];
    int b = blockIdx.x, g = blockIdx.y;
    for (int i = threadIdx.x; i < 784; i += 256) ism[i] = img[b * 784 + i];
    for (int i = threadIdx.x; i < 2592; i += 256) wsm[i] = w[g * 2592 + i];
    __syncthreads();
    for (int idx = threadIdx.x; idx < 32 * 400; idx += 256) {
        int cl = idx / 400, pix = idx - cl * 400;
        int y = pix / 20, x = pix - y * 20;
        const float* wp = &wsm[cl * 81];
        float acc = bias[g * 32 + cl];
        #pragma unroll
        for (int ky = 0; ky < 9; ky++) {
            const float* irow = &ism[(y + ky) * 28 + x];
            #pragma unroll
            for (int kx = 0; kx < 9; kx++)
                acc += irow[kx] * wp[ky * 9 + kx];
        }
        x1[(size_t)b * 102400 + (size_t)(g * 32 + cl) * 400 + pix] = fmaxf(acc, 0.f);
    }
}

// ---------------- Conv2 implicit GEMM (fp32 SGEMM 128x128x8) ----------------
// C[m][n], m=(b,oy,ox), n=co, K over (ci,ky,kx). Writes flat g_c2[b][n*36+s].
__global__ __launch_bounds__(256, 1)
void conv2_gemm_kernel(const float* __restrict__ x1, const float* __restrict__ wT,
                       const float* __restrict__ bias, float* __restrict__ out) {
    __shared__ float As[8][128];
    __shared__ float Bs[8][128];
    int tid = threadIdx.x;
    int m0 = blockIdx.y * 128;
    int n0 = blockIdx.x * 128;

    int ak = tid >> 5;               // 0..7  (k row this thread loads)
    int am = (tid & 31) * 4;         // 0..124
    int base[4];
    #pragma unroll
    for (int i = 0; i < 4; i++) {
        int m = m0 + am + i;
        int b = m / 36, s = m - b * 36;
        int oy = s / 6, ox = s - oy * 6;
        base[i] = b * 102400 + oy * 40 + ox * 2;
    }
    int bk = tid >> 5;
    int bn = (tid & 31) * 4;

    float acc[8][8];
    #pragma unroll
    for (int i = 0; i < 8; i++)
        #pragma unroll
        for (int j = 0; j < 8; j++) acc[i][j] = 0.f;

    int ty = tid >> 4, tx = tid & 15;

    for (int k0 = 0; k0 < K2; k0 += 8) {
        int k = k0 + ak;
        int ci = k / 81;
        int rem = k - ci * 81;
        int ky = rem / 9;
        int kx = rem - ky * 9;
        int off = ci * 400 + ky * 20 + kx;
        #pragma unroll
        for (int i = 0; i < 4; i++)
            As[ak][am + i] = x1[(size_t)base[i] + off];
        float4 bv = *reinterpret_cast<const float4*>(&wT[(size_t)(k0 + bk) * N2 + n0 + bn]);
        *reinterpret_cast<float4*>(&Bs[bk][bn]) = bv;
        __syncthreads();
        #pragma unroll
        for (int kk = 0; kk < 8; kk++) {
            float af[8], bf[8];
            #pragma unroll
            for (int i = 0; i < 8; i++) af[i] = As[kk][ty * 8 + i];
            #pragma unroll
            for (int j = 0; j < 8; j++) bf[j] = Bs[kk][tx * 8 + j];
            #pragma unroll
            for (int i = 0; i < 8; i++)
                #pragma unroll
                for (int j = 0; j < 8; j++)
                    acc[i][j] += af[i] * bf[j];
        }
        __syncthreads();
    }
    #pragma unroll
    for (int i = 0; i < 8; i++) {
        int m = m0 + ty * 8 + i;
        int b = m / 36, s = m - b * 36;
        #pragma unroll
        for (int j = 0; j < 8; j++) {
            int n = n0 + tx * 8 + j;
            out[(size_t)b * FLAT + n * 36 + s] = acc[i][j] + bias[n];
        }
    }
}

// ---------------- Squash u (groups of 8 consecutive, eps=1e-7) ----------------
__global__ void squash_u_kernel(const float* __restrict__ c2, float* __restrict__ u) {
    int i = blockIdx.x * 256 + threadIdx.x;
    if (i >= BATCH * ROUTES) return;
    const float4* p = reinterpret_cast<const float4*>(c2 + (size_t)i * 8);
    float4 a = p[0], b = p[1];
    float sn = a.x*a.x + a.y*a.y + a.z*a.z + a.w*a.w
             + b.x*b.x + b.y*b.y + b.z*b.z + b.w*b.w + 1e-7f;
    float sc = sqrtf(sn) / (1.f + sn);
    float4 oa = make_float4(a.x*sc, a.y*sc, a.z*sc, a.w*sc);
    float4 ob = make_float4(b.x*sc, b.y*sc, b.z*sc, b.w*sc);
    float4* q = reinterpret_cast<float4*>(u + (size_t)i * 8);
    q[0] = oa; q[1] = ob;
}

// ---------------- u_hat[b,r,k,o] = dot8(W[r,k,o,:], u[b,r,:]) ----------------
__global__ void uhat_kernel(const float* __restrict__ W, const float* __restrict__ u,
                            float* __restrict__ uhat) {
    __shared__ float Wsm[1280];
    __shared__ float usm[256];
    int r = blockIdx.x;
    int bg = blockIdx.y;   // batch group of 32
    for (int i = threadIdx.x; i < 1280; i += 256) Wsm[i] = W[(size_t)r * 1280 + i];
    if (threadIdx.x < 256) {
        int i = threadIdx.x;
        int bb = bg * 32 + (i >> 3);
        usm[i] = u[(size_t)bb * FLAT + r * 8 + (i & 7)];
    }
    __syncthreads();
    for (int i = threadIdx.x; i < 5120; i += 256) {
        int bi = i / 160, ko = i - bi * 160;
        const float* wp = &Wsm[ko * 8];
        const float* up = &usm[bi * 8];
        float acc = 0.f;
        #pragma unroll
        for (int c = 0; c < 8; c++) acc += wp[c] * up[c];
        uhat[((size_t)(bg * 32 + bi) * ROUTES + r) * 160 + ko] = acc;
    }
}

// ---------------- Routing helpers ----------------
__global__ void zero_bij_kernel(float* __restrict__ bij) {
    int i = blockIdx.x * 256 + threadIdx.x;
    if (i < ROUTES * NCAPS) bij[i] = 0.f;
}

// softmax over routes (axis 0) per capsule column k
__global__ void softmax_routes_kernel(const float* __restrict__ b, float* __restrict__ c) {
    int k = blockIdx.x;
    __shared__ float red[256];
    int tid = threadIdx.x;
    float m = -1e30f;
    for (int r = tid; r < ROUTES; r += 256) m = fmaxf(m, b[r * 10 + k]);
    red[tid] = m; __syncthreads();
    for (int s = 128; s > 0; s >>= 1) {
        if (tid < s) red[tid] = fmaxf(red[tid], red[tid + s]);
        __syncthreads();
    }
    m = red[0]; __syncthreads();
    float sum = 0.f;
    for (int r = tid; r < ROUTES; r += 256) sum += expf(b[r * 10 + k] - m);
    red[tid] = sum; __syncthreads();
    for (int s = 128; s > 0; s >>= 1) {
        if (tid < s) red[tid] += red[tid + s];
        __syncthreads();
    }
    float inv = 1.f / red[0];
    for (int r = tid; r < ROUTES; r += 256) c[r * 10 + k] = expf(b[r * 10 + k] - m) * inv;
}

// s[b,k,:] = sum_r c[r,k]*u_hat[b,r,k,:]; v = squash(s)
__global__ void sv_kernel(const float* __restrict__ cij, const float* __restrict__ uhat,
                          float* __restrict__ v) {
    int b = blockIdx.x, k = blockIdx.y;
    int tid = threadIdx.x;
    float acc[16];
    #pragma unroll
    for (int o = 0; o < 16; o++) acc[o] = 0.f;
    for (int r = tid; r < ROUTES; r += 128) {
        float cc = cij[r * 10 + k];
        const float4* p = reinterpret_cast<const float4*>(uhat + ((size_t)(b * ROUTES + r) * 10 + k) * 16);
        float4 x0 = p[0], x1 = p[1], x2 = p[2], x3 = p[3];
        acc[0]  += cc * x0.x; acc[1]  += cc * x0.y; acc[2]  += cc * x0.z; acc[3]  += cc * x0.w;
        acc[4]  += cc * x1.x; acc[5]  += cc * x1.y; acc[6]  += cc * x1.z; acc[7]  += cc * x1.w;
        acc[8]  += cc * x2.x; acc[9]  += cc * x2.y; acc[10] += cc * x2.z; acc[11] += cc * x2.w;
        acc[12] += cc * x3.x; acc[13] += cc * x3.y; acc[14] += cc * x3.z; acc[15] += cc * x3.w;
    }
    __shared__ float red[128 * 16];
    #pragma unroll
    for (int o = 0; o < 16; o++) red[tid * 16 + o] = acc[o];
    __syncthreads();
    for (int s = 64; s > 0; s >>= 1) {
        if (tid < s) {
            #pragma unroll
            for (int o = 0; o < 16; o++) red[tid * 16 + o] += red[(tid + s) * 16 + o];
        }
        __syncthreads();
    }
    if (tid == 0) {
        float sn = 0.f;
        #pragma unroll
        for (int o = 0; o < 16; o++) sn += red[o] * red[o];
        float sc = sqrtf(sn) / (1.f + sn);
        #pragma unroll
        for (int o = 0; o < 16; o++) v[(b * 10 + k) * 16 + o] = red[o] * sc;
    }
}

// b_ij[r,k] += mean_b sum_o u_hat[b,r,k,o]*v[b,k,o]
__global__ void agree_kernel(const float* __restrict__ uhat, const float* __restrict__ v,
                             float* __restrict__ bij) {
    int r = blockIdx.x, k = blockIdx.y;
    int tid = threadIdx.x;
    __shared__ __align__(16) float vsm[BATCH * 16];
    __shared__ float red[256];
    for (int i = tid; i < BATCH * 16; i += 256) {
        int bb = i >> 4, o = i & 15;
        vsm[i] = v[(bb * 10 + k) * 16 + o];
    }
    __syncthreads();
    float acc = 0.f;
    for (int bb = tid; bb < BATCH; bb += 256) {
        const float4* p = reinterpret_cast<const float4*>(uhat + ((size_t)(bb * ROUTES + r) * 10 + k) * 16);
        const float4* q = reinterpret_cast<const float4*>(&vsm[bb * 16]);
        float4 a0 = p[0], a1 = p[1], a2 = p[2], a3 = p[3];
        float4 b0 = q[0], b1 = q[1], b2 = q[2], b3 = q[3];
        acc += a0.x*b0.x + a0.y*b0.y + a0.z*b0.z + a0.w*b0.w;
        acc += a1.x*b1.x + a1.y*b1.y + a1.z*b1.z + a1.w*b1.w;
        acc += a2.x*b2.x + a2.y*b2.y + a2.z*b2.z + a2.w*b2.w;
        acc += a3.x*b3.x + a3.y*b3.y + a3.z*b3.z + a3.w*b3.w;
    }
    red[tid] = acc; __syncthreads();
    for (int s = 128; s > 0; s >>= 1) {
        if (tid < s) red[tid] += red[tid + s];
        __syncthreads();
    }
    if (tid == 0) bij[r * 10 + k] += red[0] * (1.f / (float)BATCH);
}

// ---------------- Mask / argmax / copy obj out ----------------
__global__ void mask_kernel(const float* __restrict__ v, float* __restrict__ out_obj,
                            float* __restrict__ out_mask, int* __restrict__ best) {
    int b = blockIdx.x * blockDim.x + threadIdx.x;
    if (b >= BATCH) return;
    const float* vb = v + b * 160;
    float bestn = -1.f; int bi = 0;
    #pragma unroll
    for (int k = 0; k < 10; k++) {
        float sn = 0.f;
        #pragma unroll
        for (int o = 0; o < 16; o++) { float t = vb[k * 16 + o]; sn += t * t; }
        if (sn > bestn) { bestn = sn; bi = k; }
    }
    best[b] = bi;
    for (int i = 0; i < 160; i++) out_obj[b * 160 + i] = vb[i];
    #pragma unroll
    for (int k = 0; k < 10; k++) out_mask[b * 10 + k] = (k == bi) ? 1.f : 0.f;
}

// ---------------- Decoder layer 1 (exploits one-hot mask) ----------------
__global__ void dec1_kernel(const float* __restrict__ v, const int* __restrict__ best,
                            const float* __restrict__ w1, const float* __restrict__ b1,
                            float* __restrict__ h1) {
    int b = blockIdx.x;
    int j = threadIdx.x;  // 512
    __shared__ float vs[16];
    int bi = best[b];
    if (threadIdx.x < 16) vs[threadIdx.x] = v[b * 160 + bi * 16 + threadIdx.x];
    __syncthreads();
    float acc = b1[j];
    #pragma unroll
    for (int o = 0; o < 16; o++) acc += vs[o] * w1[(bi * 16 + o) * 512 + j];
    h1[b * 512 + j] = fmaxf(acc, 0.f);
}

// ---------------- Generic small GEMM + activation (0=relu, 1=sigmoid) ----------------
template<int ACT>
__global__ void gemm_act_kernel(const float* __restrict__ A, const float* __restrict__ W,
                                const float* __restrict__ bias, float* __restrict__ C,
                                int M, int N, int K) {
    __shared__ float As[16][64];
    __shared__ float Bs[16][64];
    int tid = threadIdx.x;
    int m0 = blockIdx.y * 64, n0 = blockIdx.x * 64;
    int ty = tid >> 4, tx = tid & 15;
    float acc[4][4];
    #pragma unroll
    for (int i = 0; i < 4; i++)
        #pragma unroll
        for (int j = 0; j < 4; j++) acc[i][j] = 0.f;

    int lam = tid >> 2;            // 0..63 (m)
    int lak = (tid & 3) * 4;       // 0..12 (k)
    int lbk = tid >> 4;            // 0..15 (k)
    int lbn = (tid & 15) * 4;      // 0..60 (n)

    for (int k0 = 0; k0 < K; k0 += 16) {
        float4 av = *reinterpret_cast<const float4*>(A + (size_t)(m0 + lam) * K + k0 + lak);
        As[lak + 0][lam] = av.x; As[lak + 1][lam] = av.y;
        As[lak + 2][lam] = av.z; As[lak + 3][lam] = av.w;
        #pragma unroll
        for (int i = 0; i < 4; i++) {
            int n = n0 + lbn + i;
            Bs[lbk][lbn + i] = (n < N) ? W[(size_t)(k0 + lbk) * N + n] : 0.f;
        }
        __syncthreads();
        #pragma unroll
        for (int kk = 0; kk < 16; kk++) {
            float af[4], bf[4];
            #pragma unroll
            for (int i = 0; i < 4; i++) af[i] = As[kk][ty * 4 + i];
            #pragma unroll
            for (int j = 0; j < 4; j++) bf[j] = Bs[kk][tx * 4 + j];
            #pragma unroll
            for (int i = 0; i < 4; i++)
                #pragma unroll
                for (int j = 0; j < 4; j++)
                    acc[i][j] += af[i] * bf[j];
        }
        __syncthreads();
    }
    #pragma unroll
    for (int i = 0; i < 4; i++) {
        int m = m0 + ty * 4 + i;
        #pragma unroll
        for (int j = 0; j < 4; j++) {
            int n = n0 + tx * 4 + j;
            if (n < N) {
                float x = acc[i][j] + bias[n];
                if (ACT == 0) x = fmaxf(x, 0.f);
                else          x = 1.f / (1.f + expf(-x));
                C[(size_t)m * N + n] = x;
            }
        }
    }
}

// ---------------- Host launcher ----------------
extern "C" void kernel_launch(void* const* d_in, const int* in_sizes, int n_in,
                              void* d_out, int out_size) {
    const float* image  = (const float*)d_in[0];
    const float* conv_w = (const float*)d_in[1];
    const float* conv_b = (const float*)d_in[2];
    const float* pc_w   = (const float*)d_in[3];
    const float* pc_b   = (const float*)d_in[4];
    const float* W_obj  = (const float*)d_in[5];
    const float* dec_w1 = (const float*)d_in[6];
    const float* dec_b1 = (const float*)d_in[7];
    const float* dec_w2 = (const float*)d_in[8];
    const float* dec_b2 = (const float*)d_in[9];
    const float* dec_w3 = (const float*)d_in[10];
    const float* dec_b3 = (const float*)d_in[11];

    float* out = (float*)d_out;
    float* out_obj  = out;                       // 512*160
    float* out_rec  = out + BATCH * 160;         // 512*784
    float* out_mask = out + BATCH * (160 + 784); // 512*10

    float* x1   = nullptr; cudaGetSymbolAddress((void**)&x1,   g_x1);
    float* wT   = nullptr; cudaGetSymbolAddress((void**)&wT,   g_wT);
    float* c2   = nullptr; cudaGetSymbolAddress((void**)&c2,   g_c2);
    float* u    = nullptr; cudaGetSymbolAddress((void**)&u,    g_u);
    float* uhat = nullptr; cudaGetSymbolAddress((void**)&uhat, g_uhat);
    float* bij  = nullptr; cudaGetSymbolAddress((void**)&bij,  g_bij);
    float* cij  = nullptr; cudaGetSymbolAddress((void**)&cij,  g_cij);
    float* v    = nullptr; cudaGetSymbolAddress((void**)&v,    g_v);
    int*   best = nullptr; cudaGetSymbolAddress((void**)&best, g_best);
    float* h1   = nullptr; cudaGetSymbolAddress((void**)&h1,   g_h1);
    float* h2   = nullptr; cudaGetSymbolAddress((void**)&h2,   g_h2);

    // 1) transpose pc_w -> wT[k][n]
    transpose_w_kernel<<<dim3(K2 / 32, N2 / 32), dim3(32, 8)>>>(pc_w, wT);
    // 2) conv1 + relu
    conv1_kernel<<<dim3(BATCH, 8), 256>>>(image, conv_w, conv_b, x1);
    // 3) conv2 as implicit GEMM
    conv2_gemm_kernel<<<dim3(N2 / 128, M2 / 128), 256>>>(x1, wT, pc_b, c2);
    // 4) squash -> u
    squash_u_kernel<<<(BATCH * ROUTES + 255) / 256, 256>>>(c2, u);
    // 5) u_hat
    uhat_kernel<<<dim3(ROUTES, BATCH / 32), 256>>>(W_obj, u, uhat);
    // 6) routing (3 iterations)
    zero_bij_kernel<<<(ROUTES * NCAPS + 255) / 256, 256>>>(bij);
    for (int it = 0; it < 3; it++) {
        softmax_routes_kernel<<<NCAPS, 256>>>(bij, cij);
        sv_kernel<<<dim3(BATCH, NCAPS), 128>>>(cij, uhat, v);
        if (it < 2)
            agree_kernel<<<dim3(ROUTES, NCAPS), 256>>>(uhat, v, bij);
    }
    // 7) mask + obj output
    mask_kernel<<<2, 256>>>(v, out_obj, out_mask, best);
    // 8) decoder
    dec1_kernel<<<BATCH, 512>>>(v, best, dec_w1, dec_b1, h1);
    gemm_act_kernel<0><<<dim3(1024 / 64, BATCH / 64), 256>>>(h1, dec_w2, dec_b2, h2, BATCH, 1024, 512);
    gemm_act_kernel<1><<<dim3((784 + 63) / 64, BATCH / 64), 256>>>(h2, dec_w3, dec_b3, out_rec, BATCH, 784, 1024);
}

// round 2
// speedup vs baseline: 1.0026x; 1.0026x over previous
#include <cuda_runtime.h>
#include <math.h>

// ---------------- Problem constants ----------------
#define BATCH 512
#define C1 256            // conv1 out channels
#define H1 20             // conv1 out spatial
#define ROUTES 1152
#define PCAPS 8
#define NCAPS 10
#define CAPDIM 16
#define M2 (BATCH*36)     // 18432
#define K2 (256*81)       // 20736
#define N2 256
#define FLAT 9216         // 256*36 per batch

// ---------------- Device scratch (no allocations allowed) ----------------
__device__ __align__(16) float g_x1[BATCH*C1*H1*H1];     // conv1 out  (210MB)
__device__ __align__(16) float g_wT[K2*N2];              // transposed pc_w (21MB)
__device__ __align__(16) float g_c2[BATCH*FLAT];         // conv2 out flat (19MB)
__device__ __align__(16) float g_u[BATCH*FLAT];          // squashed u
__device__ __align__(16) float g_uhat[BATCH*ROUTES*NCAPS*CAPDIM]; // 377MB
__device__ __align__(16) float g_bij[ROUTES*NCAPS];
__device__ __align__(16) float g_cij[ROUTES*NCAPS];
__device__ __align__(16) float g_v[BATCH*NCAPS*CAPDIM];
__device__ int   g_best[BATCH];
__device__ __align__(16) float g_h1[BATCH*512];
__device__ __align__(16) float g_h2[BATCH*1024];

// ---------------- Weight transpose: wT[k][n] = pc_w[n][k] ----------------
__global__ void transpose_w_kernel(const float* __restrict__ w, float* __restrict__ wT) {
    __shared__ float t[32][33];
    int k0 = blockIdx.x * 32, n0 = blockIdx.y * 32;
    int tx = threadIdx.x, ty = threadIdx.y;   // 32 x 8
    #pragma unroll
    for (int i = ty; i < 32; i += 8)
        t[i][tx] = w[(size_t)(n0 + i) * K2 + k0 + tx];
    __syncthreads();
    #pragma unroll
    for (int i = ty; i < 32; i += 8)
        wT[(size_t)(k0 + i) * N2 + n0 + tx] = t[tx][i];
}

// ---------------- Conv1: 1->256, 9x9, stride1, relu ----------------
__global__ void conv1_kernel(const float* __restrict__ img, const float* __restrict__ w,
                             const float* __restrict__ bias, float* __restrict__ x1) {
    __shared__ float ism[784];
    __shared__ float wsm[32 * 81];
    int b = blockIdx.x, g = blockIdx.y;
    for (int i = threadIdx.x; i < 784; i += 256) ism[i] = img[b * 784 + i];
    for (int i = threadIdx.x; i < 2592; i += 256) wsm[i] = w[g * 2592 + i];
    __syncthreads();
    for (int idx = threadIdx.x; idx < 32 * 400; idx += 256) {
        int cl = idx / 400, pix = idx - cl * 400;
        int y = pix / 20, x = pix - y * 20;
        const float* wp = &wsm[cl * 81];
        float acc = bias[g * 32 + cl];
        #pragma unroll
        for (int ky = 0; ky < 9; ky++) {
            const float* irow = &ism[(y + ky) * 28 + x];
            #pragma unroll
            for (int kx = 0; kx < 9; kx++)
                acc += irow[kx] * wp[ky * 9 + kx];
        }
        x1[(size_t)b * 102400 + (size_t)(g * 32 + cl) * 400 + pix] = fmaxf(acc, 0.f);
    }
}

// ---------------- Conv2 implicit GEMM (fp32 SGEMM 128x128x8) ----------------
// C[m][n], m=(b,oy,ox), n=co, K over (ci,ky,kx). Writes flat g_c2[b][n*36+s].
__global__ __launch_bounds__(256, 1)
void conv2_gemm_kernel(const float* __restrict__ x1, const float* __restrict__ wT,
                       const float* __restrict__ bias, float* __restrict__ out) {
    __shared__ float As[8][128];
    __shared__ float Bs[8][128];
    int tid = threadIdx.x;
    int m0 = blockIdx.y * 128;
    int n0 = blockIdx.x * 128;

    int ak = tid >> 5;               // 0..7  (k row this thread loads)
    int am = (tid & 31) * 4;         // 0..124
    int base[4];
    #pragma unroll
    for (int i = 0; i < 4; i++) {
        int m = m0 + am + i;
        int b = m / 36, s = m - b * 36;
        int oy = s / 6, ox = s - oy * 6;
        base[i] = b * 102400 + oy * 40 + ox * 2;
    }
    int bk = tid >> 5;
    int bn = (tid & 31) * 4;

    float acc[8][8];
    #pragma unroll
    for (int i = 0; i < 8; i++)
        #pragma unroll
        for (int j = 0; j < 8; j++) acc[i][j] = 0.f;

    int ty = tid >> 4, tx = tid & 15;

    for (int k0 = 0; k0 < K2; k0 += 8) {
        int k = k0 + ak;
        int ci = k / 81;
        int rem = k - ci * 81;
        int ky = rem / 9;
        int kx = rem - ky * 9;
        int off = ci * 400 + ky * 20 + kx;
        #pragma unroll
        for (int i = 0; i < 4; i++)
            As[ak][am + i] = x1[(size_t)base[i] + off];
        float4 bv = *reinterpret_cast<const float4*>(&wT[(size_t)(k0 + bk) * N2 + n0 + bn]);
        *reinterpret_cast<float4*>(&Bs[bk][bn]) = bv;
        __syncthreads();
        #pragma unroll
        for (int kk = 0; kk < 8; kk++) {
            float af[8], bf[8];
            #pragma unroll
            for (int i = 0; i < 8; i++) af[i] = As[kk][ty * 8 + i];
            #pragma unroll
            for (int j = 0; j < 8; j++) bf[j] = Bs[kk][tx * 8 + j];
            #pragma unroll
            for (int i = 0; i < 8; i++)
                #pragma unroll
                for (int j = 0; j < 8; j++)
                    acc[i][j] += af[i] * bf[j];
        }
        __syncthreads();
    }
    #pragma unroll
    for (int i = 0; i < 8; i++) {
        int m = m0 + ty * 8 + i;
        int b = m / 36, s = m - b * 36;
        #pragma unroll
        for (int j = 0; j < 8; j++) {
            int n = n0 + tx * 8 + j;
            out[(size_t)b * FLAT + n * 36 + s] = acc[i][j] + bias[n];
        }
    }
}

// ---------------- Squash u (groups of 8 consecutive, eps=1e-7) ----------------
__global__ void squash_u_kernel(const float* __restrict__ c2, float* __restrict__ u) {
    int i = blockIdx.x * 256 + threadIdx.x;
    if (i >= BATCH * ROUTES) return;
    const float4* p = reinterpret_cast<const float4*>(c2 + (size_t)i * 8);
    float4 a = p[0], b = p[1];
    float sn = a.x*a.x + a.y*a.y + a.z*a.z + a.w*a.w
             + b.x*b.x + b.y*b.y + b.z*b.z + b.w*b.w + 1e-7f;
    float sc = sqrtf(sn) / (1.f + sn);
    float4 oa = make_float4(a.x*sc, a.y*sc, a.z*sc, a.w*sc);
    float4 ob = make_float4(b.x*sc, b.y*sc, b.z*sc, b.w*sc);
    float4* q = reinterpret_cast<float4*>(u + (size_t)i * 8);
    q[0] = oa; q[1] = ob;
}

// ---------------- u_hat[b,r,k,o] = dot8(W[r,k,o,:], u[b,r,:]) ----------------
__global__ void uhat_kernel(const float* __restrict__ W, const float* __restrict__ u,
                            float* __restrict__ uhat) {
    __shared__ float Wsm[1280];
    __shared__ float usm[256];
    int r = blockIdx.x;
    int bg = blockIdx.y;   // batch group of 32
    for (int i = threadIdx.x; i < 1280; i += 256) Wsm[i] = W[(size_t)r * 1280 + i];
    if (threadIdx.x < 256) {
        int i = threadIdx.x;
        int bb = bg * 32 + (i >> 3);
        usm[i] = u[(size_t)bb * FLAT + r * 8 + (i & 7)];
    }
    __syncthreads();
    for (int i = threadIdx.x; i < 5120; i += 256) {
        int bi = i / 160, ko = i - bi * 160;
        const float* wp = &Wsm[ko * 8];
        const float* up = &usm[bi * 8];
        float acc = 0.f;
        #pragma unroll
        for (int c = 0; c < 8; c++) acc += wp[c] * up[c];
        uhat[((size_t)(bg * 32 + bi) * ROUTES + r) * 160 + ko] = acc;
    }
}

// ---------------- Routing helpers ----------------
__global__ void zero_bij_kernel(float* __restrict__ bij) {
    int i = blockIdx.x * 256 + threadIdx.x;
    if (i < ROUTES * NCAPS) bij[i] = 0.f;
}

// softmax over routes (axis 0) per capsule column k
__global__ void softmax_routes_kernel(const float* __restrict__ b, float* __restrict__ c) {
    int k = blockIdx.x;
    __shared__ float red[256];
    int tid = threadIdx.x;
    float m = -1e30f;
    for (int r = tid; r < ROUTES; r += 256) m = fmaxf(m, b[r * 10 + k]);
    red[tid] = m; __syncthreads();
    for (int s = 128; s > 0; s >>= 1) {
        if (tid < s) red[tid] = fmaxf(red[tid], red[tid + s]);
        __syncthreads();
    }
    m = red[0]; __syncthreads();
    float sum = 0.f;
    for (int r = tid; r < ROUTES; r += 256) sum += expf(b[r * 10 + k] - m);
    red[tid] = sum; __syncthreads();
    for (int s = 128; s > 0; s >>= 1) {
        if (tid < s) red[tid] += red[tid + s];
        __syncthreads();
    }
    float inv = 1.f / red[0];
    for (int r = tid; r < ROUTES; r += 256) c[r * 10 + k] = expf(b[r * 10 + k] - m) * inv;
}

// s[b,k,:] = sum_r c[r,k]*u_hat[b,r,k,:]; v = squash(s)
__global__ void sv_kernel(const float* __restrict__ cij, const float* __restrict__ uhat,
                          float* __restrict__ v) {
    int b = blockIdx.x, k = blockIdx.y;
    int tid = threadIdx.x;
    float acc[16];
    #pragma unroll
    for (int o = 0; o < 16; o++) acc[o] = 0.f;
    for (int r = tid; r < ROUTES; r += 128) {
        float cc = cij[r * 10 + k];
        const float4* p = reinterpret_cast<const float4*>(uhat + ((size_t)(b * ROUTES + r) * 10 + k) * 16);
        float4 x0 = p[0], x1 = p[1], x2 = p[2], x3 = p[3];
        acc[0]  += cc * x0.x; acc[1]  += cc * x0.y; acc[2]  += cc * x0.z; acc[3]  += cc * x0.w;
        acc[4]  += cc * x1.x; acc[5]  += cc * x1.y; acc[6]  += cc * x1.z; acc[7]  += cc * x1.w;
        acc[8]  += cc * x2.x; acc[9]  += cc * x2.y; acc[10] += cc * x2.z; acc[11] += cc * x2.w;
        acc[12] += cc * x3.x; acc[13] += cc * x3.y; acc[14] += cc * x3.z; acc[15] += cc * x3.w;
    }
    __shared__ float red[128 * 16];
    #pragma unroll
    for (int o = 0; o < 16; o++) red[tid * 16 + o] = acc[o];
    __syncthreads();
    for (int s = 64; s > 0; s >>= 1) {
        if (tid < s) {
            #pragma unroll
            for (int o = 0; o < 16; o++) red[tid * 16 + o] += red[(tid + s) * 16 + o];
        }
        __syncthreads();
    }
    if (tid == 0) {
        float sn = 0.f;
        #pragma unroll
        for (int o = 0; o < 16; o++) sn += red[o] * red[o];
        float sc = sqrtf(sn) / (1.f + sn);
        #pragma unroll
        for (int o = 0; o < 16; o++) v[(b * 10 + k) * 16 + o] = red[o] * sc;
    }
}

// b_ij[r,k] += mean_b sum_o u_hat[b,r,k,o]*v[b,k,o]
__global__ void agree_kernel(const float* __restrict__ uhat, const float* __restrict__ v,
                             float* __restrict__ bij) {
    int r = blockIdx.x, k = blockIdx.y;
    int tid = threadIdx.x;
    __shared__ __align__(16) float vsm[BATCH * 16];
    __shared__ float red[256];
    for (int i = tid; i < BATCH * 16; i += 256) {
        int bb = i >> 4, o = i & 15;
        vsm[i] = v[(bb * 10 + k) * 16 + o];
    }
    __syncthreads();
    float acc = 0.f;
    for (int bb = tid; bb < BATCH; bb += 256) {
        const float4* p = reinterpret_cast<const float4*>(uhat + ((size_t)(bb * ROUTES + r) * 10 + k) * 16);
        const float4* q = reinterpret_cast<const float4*>(&vsm[bb * 16]);
        float4 a0 = p[0], a1 = p[1], a2 = p[2], a3 = p[3];
        float4 b0 = q[0], b1 = q[1], b2 = q[2], b3 = q[3];
        acc += a0.x*b0.x + a0.y*b0.y + a0.z*b0.z + a0.w*b0.w;
        acc += a1.x*b1.x + a1.y*b1.y + a1.z*b1.z + a1.w*b1.w;
        acc += a2.x*b2.x + a2.y*b2.y + a2.z*b2.z + a2.w*b2.w;
        acc += a3.x*b3.x + a3.y*b3.y + a3.z*b3.z + a3.w*b3.w;
    }
    red[tid] = acc; __syncthreads();
    for (int s = 128; s > 0; s >>= 1) {
        if (tid < s) red[tid] += red[tid + s];
        __syncthreads();
    }
    if (tid == 0) bij[r * 10 + k] += red[0] * (1.f / (float)BATCH);
}

// ---------------- Mask / argmax / copy obj out ----------------
__global__ void mask_kernel(const float* __restrict__ v, float* __restrict__ out_obj,
                            float* __restrict__ out_mask, int* __restrict__ best) {
    int b = blockIdx.x * blockDim.x + threadIdx.x;
    if (b >= BATCH) return;
    const float* vb = v + b * 160;
    float bestn = -1.f; int bi = 0;
    #pragma unroll
    for (int k = 0; k < 10; k++) {
        float sn = 0.f;
        #pragma unroll
        for (int o = 0; o < 16; o++) { float t = vb[k * 16 + o]; sn += t * t; }
        if (sn > bestn) { bestn = sn; bi = k; }
    }
    best[b] = bi;
    for (int i = 0; i < 160; i++) out_obj[b * 160 + i] = vb[i];
    #pragma unroll
    for (int k = 0; k < 10; k++) out_mask[b * 10 + k] = (k == bi) ? 1.f : 0.f;
}

// ---------------- Decoder layer 1 (exploits one-hot mask) ----------------
__global__ void dec1_kernel(const float* __restrict__ v, const int* __restrict__ best,
                            const float* __restrict__ w1, const float* __restrict__ b1,
                            float* __restrict__ h1) {
    int b = blockIdx.x;
    int j = threadIdx.x;  // 512
    __shared__ float vs[16];
    int bi = best[b];
    if (threadIdx.x < 16) vs[threadIdx.x] = v[b * 160 + bi * 16 + threadIdx.x];
    __syncthreads();
    float acc = b1[j];
    #pragma unroll
    for (int o = 0; o < 16; o++) acc += vs[o] * w1[(bi * 16 + o) * 512 + j];
    h1[b * 512 + j] = fmaxf(acc, 0.f);
}

// ---------------- Generic small GEMM + activation (0=relu, 1=sigmoid) ----------------
template<int ACT>
__global__ void gemm_act_kernel(const float* __restrict__ A, const float* __restrict__ W,
                                const float* __restrict__ bias, float* __restrict__ C,
                                int M, int N, int K) {
    __shared__ float As[16][64];
    __shared__ float Bs[16][64];
    int tid = threadIdx.x;
    int m0 = blockIdx.y * 64, n0 = blockIdx.x * 64;
    int ty = tid >> 4, tx = tid & 15;
    float acc[4][4];
    #pragma unroll
    for (int i = 0; i < 4; i++)
        #pragma unroll
        for (int j = 0; j < 4; j++) acc[i][j] = 0.f;

    int lam = tid >> 2;            // 0..63 (m)
    int lak = (tid & 3) * 4;       // 0..12 (k)
    int lbk = tid >> 4;            // 0..15 (k)
    int lbn = (tid & 15) * 4;      // 0..60 (n)

    for (int k0 = 0; k0 < K; k0 += 16) {
        float4 av = *reinterpret_cast<const float4*>(A + (size_t)(m0 + lam) * K + k0 + lak);
        As[lak + 0][lam] = av.x; As[lak + 1][lam] = av.y;
        As[lak + 2][lam] = av.z; As[lak + 3][lam] = av.w;
        #pragma unroll
        for (int i = 0; i < 4; i++) {
            int n = n0 + lbn + i;
            Bs[lbk][lbn + i] = (n < N) ? W[(size_t)(k0 + lbk) * N + n] : 0.f;
        }
        __syncthreads();
        #pragma unroll
        for (int kk = 0; kk < 16; kk++) {
            float af[4], bf[4];
            #pragma unroll
            for (int i = 0; i < 4; i++) af[i] = As[kk][ty * 4 + i];
            #pragma unroll
            for (int j = 0; j < 4; j++) bf[j] = Bs[kk][tx * 4 + j];
            #pragma unroll
            for (int i = 0; i < 4; i++)
                #pragma unroll
                for (int j = 0; j < 4; j++)
                    acc[i][j] += af[i] * bf[j];
        }
        __syncthreads();
    }
    #pragma unroll
    for (int i = 0; i < 4; i++) {
        int m = m0 + ty * 4 + i;
        #pragma unroll
        for (int j = 0; j < 4; j++) {
            int n = n0 + tx * 4 + j;
            if (n < N) {
                float x = acc[i][j] + bias[n];
                if (ACT == 0) x = fmaxf(x, 0.f);
                else          x = 1.f / (1.f + expf(-x));
                C[(size_t)m * N + n] = x;
            }
        }
    }
}

// ---------------- Host launcher ----------------
extern "C" void kernel_launch(void* const* d_in, const int* in_sizes, int n_in,
                              void* d_out, int out_size) {
    const float* image  = (const float*)d_in[0];
    const float* conv_w = (const float*)d_in[1];
    const float* conv_b = (const float*)d_in[2];
    const float* pc_w   = (const float*)d_in[3];
    const float* pc_b   = (const float*)d_in[4];
    const float* W_obj  = (const float*)d_in[5];
    const float* dec_w1 = (const float*)d_in[6];
    const float* dec_b1 = (const float*)d_in[7];
    const float* dec_w2 = (const float*)d_in[8];
    const float* dec_b2 = (const float*)d_in[9];
    const float* dec_w3 = (const float*)d_in[10];
    const float* dec_b3 = (const float*)d_in[11];

    float* out = (float*)d_out;
    float* out_obj  = out;                       // 512*160
    float* out_rec  = out + BATCH * 160;         // 512*784
    float* out_mask = out + BATCH * (160 + 784); // 512*10

    float* x1   = nullptr; cudaGetSymbolAddress((void**)&x1,   g_x1);
    float* wT   = nullptr; cudaGetSymbolAddress((void**)&wT,   g_wT);
    float* c2   = nullptr; cudaGetSymbolAddress((void**)&c2,   g_c2);
    float* u    = nullptr; cudaGetSymbolAddress((void**)&u,    g_u);
    float* uhat = nullptr; cudaGetSymbolAddress((void**)&uhat, g_uhat);
    float* bij  = nullptr; cudaGetSymbolAddress((void**)&bij,  g_bij);
    float* cij  = nullptr; cudaGetSymbolAddress((void**)&cij,  g_cij);
    float* v    = nullptr; cudaGetSymbolAddress((void**)&v,    g_v);
    int*   best = nullptr; cudaGetSymbolAddress((void**)&best, g_best);
    float* h1   = nullptr; cudaGetSymbolAddress((void**)&h1,   g_h1);
    float* h2   = nullptr; cudaGetSymbolAddress((void**)&h2,   g_h2);

    // 1) transpose pc_w -> wT[k][n]
    transpose_w_kernel<<<dim3(K2 / 32, N2 / 32), dim3(32, 8)>>>(pc_w, wT);
    // 2) conv1 + relu
    conv1_kernel<<<dim3(BATCH, 8), 256>>>(image, conv_w, conv_b, x1);
    // 3) conv2 as implicit GEMM
    conv2_gemm_kernel<<<dim3(N2 / 128, M2 / 128), 256>>>(x1, wT, pc_b, c2);
    // 4) squash -> u
    squash_u_kernel<<<(BATCH * ROUTES + 255) / 256, 256>>>(c2, u);
    // 5) u_hat
    uhat_kernel<<<dim3(ROUTES, BATCH / 32), 256>>>(W_obj, u, uhat);
    // 6) routing (3 iterations)
    zero_bij_kernel<<<(ROUTES * NCAPS + 255) / 256, 256>>>(bij);
    for (int it = 0; it < 3; it++) {
        softmax_routes_kernel<<<NCAPS, 256>>>(bij, cij);
        sv_kernel<<<dim3(BATCH, NCAPS), 128>>>(cij, uhat, v);
        if (it < 2)
            agree_kernel<<<dim3(ROUTES, NCAPS), 256>>>(uhat, v, bij);
    }
    // 7) mask + obj output
    mask_kernel<<<2, 256>>>(v, out_obj, out_mask, best);
    // 8) decoder
    dec1_kernel<<<BATCH, 512>>>(v, best, dec_w1, dec_b1, h1);
    gemm_act_kernel<0><<<dim3(1024 / 64, BATCH / 64), 256>>>(h1, dec_w2, dec_b2, h2, BATCH, 1024, 512);
    gemm_act_kernel<1><<<dim3((784 + 63) / 64, BATCH / 64), 256>>>(h2, dec_w3, dec_b3, out_rec, BATCH, 784, 1024);
}

// round 4
// speedup vs baseline: 1.8873x; 1.8825x over previous
#include <cuda_runtime.h>
#include <cuda_bf16.h>
#include <stdint.h>
#include <math.h>

// ---------------- Problem constants ----------------
#define BATCH 512
#define C1 256
#define ROUTES 1152
#define NCAPS 10
#define CAPDIM 16
#define M2 (BATCH*36)     // 18432
#define K2 (256*81)       // 20736
#define N2 256
#define FLAT 9216

// ---------------- Device scratch ----------------
__device__ __align__(16) float g_x1[BATCH*C1*20*20];     // conv1 out (210MB)
__device__ __align__(16) float g_c2[BATCH*FLAT];
__device__ __align__(16) float g_u[BATCH*FLAT];
__device__ __align__(16) float g_uhat[(size_t)BATCH*ROUTES*NCAPS*CAPDIM];
__device__ __align__(16) float g_bij[ROUTES*NCAPS];
__device__ __align__(16) float g_cij[ROUTES*NCAPS];
__device__ __align__(16) float g_v[BATCH*NCAPS*CAPDIM];
__device__ int   g_best[BATCH];
__device__ __align__(16) float g_h1[BATCH*512];
__device__ __align__(16) float g_h2[BATCH*1024];

// ---------------- Conv1: 1->256, 9x9, stride1, relu ----------------
__global__ void conv1_kernel(const float* __restrict__ img, const float* __restrict__ w,
                             const float* __restrict__ bias, float* __restrict__ x1) {
    __shared__ float ism[784];
    __shared__ float wsm[32 * 81];
    int b = blockIdx.x, g = blockIdx.y;
    for (int i = threadIdx.x; i < 784; i += 256) ism[i] = img[b * 784 + i];
    for (int i = threadIdx.x; i < 2592; i += 256) wsm[i] = w[g * 2592 + i];
    __syncthreads();
    for (int idx = threadIdx.x; idx < 32 * 400; idx += 256) {
        int cl = idx / 400, pix = idx - cl * 400;
        int y = pix / 20, x = pix - y * 20;
        const float* wp = &wsm[cl * 81];
        float acc = bias[g * 32 + cl];
        #pragma unroll
        for (int ky = 0; ky < 9; ky++) {
            const float* irow = &ism[(y + ky) * 28 + x];
            #pragma unroll
            for (int kx = 0; kx < 9; kx++)
                acc += irow[kx] * wp[ky * 9 + kx];
        }
        x1[(size_t)b * 102400 + (size_t)(g * 32 + cl) * 400 + pix] = fmaxf(acc, 0.f);
    }
}

// ---------------- Conv2 implicit GEMM via split-bf16 tensor-core MMA ----------------
// C = A(im2col of x1, MxK) * B^T (pc_w is [N][K] row-major, used as col-major B)
// Precision: fp32 ~= hi + lo (bf16 each); C = Ah*Bh + Ah*Bl + Al*Bh
#define BK 16
#define LDS_PAD 24   // row stride in bf16 elems (conflict-free for frag pattern)

__device__ __forceinline__ void mma_bf16(float& c0, float& c1, float& c2, float& c3,
                                         uint32_t a0, uint32_t a1, uint32_t a2, uint32_t a3,
                                         uint32_t b0, uint32_t b1) {
    asm volatile(
        "mma.sync.aligned.m16n8k16.row.col.f32.bf16.bf16.f32 "
        "{%0,%1,%2,%3}, {%4,%5,%6,%7}, {%8,%9}, {%0,%1,%2,%3};\n"
        : "+f"(c0), "+f"(c1), "+f"(c2), "+f"(c3)
        : "r"(a0), "r"(a1), "r"(a2), "r"(a3), "r"(b0), "r"(b1));
}

__device__ __forceinline__ void split_bf16(float x, __nv_bfloat16& h, __nv_bfloat16& l) {
    h = __float2bfloat16(x);
    l = __float2bfloat16(x - __bfloat162float(h));
}

__global__ __launch_bounds__(256, 1)
void conv2_mma_kernel(const float* __restrict__ x1, const float* __restrict__ pcw,
                      const float* __restrict__ bias, float* __restrict__ out) {
    __shared__ __align__(16) __nv_bfloat16 AsH[2][128 * LDS_PAD];
    __shared__ __align__(16) __nv_bfloat16 AsL[2][128 * LDS_PAD];
    __shared__ __align__(16) __nv_bfloat16 BsH[2][128 * LDS_PAD];
    __shared__ __align__(16) __nv_bfloat16 BsL[2][128 * LDS_PAD];

    const int t = threadIdx.x;
    const int m0 = blockIdx.y * 128;
    const int n0 = blockIdx.x * 128;

    // --- loader mapping: each thread owns one row (m and n = t>>1) and one k-half ---
    const int lr  = t >> 1;          // 0..127
    const int lkh = (t & 1) * 8;     // 0 or 8

    const int mg = m0 + lr;
    const int bb = mg / 36;
    const int ss = mg - bb * 36;
    const int oy = ss / 6, ox = ss - oy * 6;
    const float* abase = x1 + (size_t)bb * 102400 + oy * 40 + ox * 2;
    const float* bbase = pcw + (size_t)(n0 + lr) * K2 + lkh;

    // --- compute mapping ---
    const int wid = t >> 5;
    const int wm = wid >> 2;          // 0..1
    const int wn = wid & 3;           // 0..3
    const int lane = t & 31;
    const int qr = lane >> 2;         // 0..7
    const int qc = (lane & 3) * 2;    // 0,2,4,6

    float acc[4][4][4];
    #pragma unroll
    for (int i = 0; i < 4; i++)
        #pragma unroll
        for (int j = 0; j < 4; j++)
            #pragma unroll
            for (int r = 0; r < 4; r++) acc[i][j][r] = 0.f;

    float af[8];
    float bf[8];

    // prologue: load k-step 0
    {
        #pragma unroll
        for (int j = 0; j < 8; j++) {
            int k = lkh + j;
            int ci = k / 81, rem = k - ci * 81;
            int ky = rem / 9, kx = rem - ky * 9;
            af[j] = abase[ci * 400 + ky * 20 + kx];
        }
        float4 v0 = *reinterpret_cast<const float4*>(bbase);
        float4 v1 = *reinterpret_cast<const float4*>(bbase + 4);
        bf[0]=v0.x; bf[1]=v0.y; bf[2]=v0.z; bf[3]=v0.w;
        bf[4]=v1.x; bf[5]=v1.y; bf[6]=v1.z; bf[7]=v1.w;
        int sa = lr * LDS_PAD + lkh;
        #pragma unroll
        for (int j = 0; j < 8; j++) {
            __nv_bfloat16 h, l;
            split_bf16(af[j], h, l); AsH[0][sa + j] = h; AsL[0][sa + j] = l;
            split_bf16(bf[j], h, l); BsH[0][sa + j] = h; BsL[0][sa + j] = l;
        }
    }
    __syncthreads();

    const int NSTEP = K2 / BK;   // 1296
    for (int s = 0; s < NSTEP; s++) {
        const int cur = s & 1;
        const bool more = (s + 1 < NSTEP);
        // prefetch next k-step into registers
        if (more) {
            int k0 = (s + 1) * BK;
            #pragma unroll
            for (int j = 0; j < 8; j++) {
                int k = k0 + lkh + j;
                int ci = k / 81, rem = k - ci * 81;
                int ky = rem / 9, kx = rem - ky * 9;
                af[j] = abase[ci * 400 + ky * 20 + kx];
            }
            float4 v0 = *reinterpret_cast<const float4*>(bbase + k0);
            float4 v1 = *reinterpret_cast<const float4*>(bbase + k0 + 4);
            bf[0]=v0.x; bf[1]=v0.y; bf[2]=v0.z; bf[3]=v0.w;
            bf[4]=v1.x; bf[5]=v1.y; bf[6]=v1.z; bf[7]=v1.w;
        }

        // compute on stage `cur`
        {
            uint32_t ah[4][4], al[4][4], bh[4][2], bl[4][2];
            #pragma unroll
            for (int i = 0; i < 4; i++) {
                int r0 = (wm * 64 + i * 16 + qr) * LDS_PAD;
                int r8 = r0 + 8 * LDS_PAD;
                ah[i][0] = *reinterpret_cast<const uint32_t*>(&AsH[cur][r0 + qc]);
                ah[i][1] = *reinterpret_cast<const uint32_t*>(&AsH[cur][r8 + qc]);
                ah[i][2] = *reinterpret_cast<const uint32_t*>(&AsH[cur][r0 + qc + 8]);
                ah[i][3] = *reinterpret_cast<const uint32_t*>(&AsH[cur][r8 + qc + 8]);
                al[i][0] = *reinterpret_cast<const uint32_t*>(&AsL[cur][r0 + qc]);
                al[i][1] = *reinterpret_cast<const uint32_t*>(&AsL[cur][r8 + qc]);
                al[i][2] = *reinterpret_cast<const uint32_t*>(&AsL[cur][r0 + qc + 8]);
                al[i][3] = *reinterpret_cast<const uint32_t*>(&AsL[cur][r8 + qc + 8]);
            }
            #pragma unroll
            for (int j = 0; j < 4; j++) {
                int nr = (wn * 32 + j * 8 + qr) * LDS_PAD;
                bh[j][0] = *reinterpret_cast<const uint32_t*>(&BsH[cur][nr + qc]);
                bh[j][1] = *reinterpret_cast<const uint32_t*>(&BsH[cur][nr + qc + 8]);
                bl[j][0] = *reinterpret_cast<const uint32_t*>(&BsL[cur][nr + qc]);
                bl[j][1] = *reinterpret_cast<const uint32_t*>(&BsL[cur][nr + qc + 8]);
            }
            #pragma unroll
            for (int i = 0; i < 4; i++)
                #pragma unroll
                for (int j = 0; j < 4; j++) {
                    mma_bf16(acc[i][j][0], acc[i][j][1], acc[i][j][2], acc[i][j][3],
                             ah[i][0], ah[i][1], ah[i][2], ah[i][3], bh[j][0], bh[j][1]);
                    mma_bf16(acc[i][j][0], acc[i][j][1], acc[i][j][2], acc[i][j][3],
                             ah[i][0], ah[i][1], ah[i][2], ah[i][3], bl[j][0], bl[j][1]);
                    mma_bf16(acc[i][j][0], acc[i][j][1], acc[i][j][2], acc[i][j][3],
                             al[i][0], al[i][1], al[i][2], al[i][3], bh[j][0], bh[j][1]);
                }
        }

        // store prefetched regs into the other stage
        if (more) {
            int nxt = cur ^ 1;
            int sa = lr * LDS_PAD + lkh;
            #pragma unroll
            for (int j = 0; j < 8; j++) {
                __nv_bfloat16 h, l;
                split_bf16(af[j], h, l); AsH[nxt][sa + j] = h; AsL[nxt][sa + j] = l;
                split_bf16(bf[j], h, l); BsH[nxt][sa + j] = h; BsL[nxt][sa + j] = l;
            }
        }
        __syncthreads();
    }

    // epilogue: C[m][n] -> out[b*FLAT + n*36 + s] + bias[n]
    #pragma unroll
    for (int i = 0; i < 4; i++) {
        #pragma unroll
        for (int j = 0; j < 4; j++) {
            int r = m0 + wm * 64 + i * 16 + qr;
            int c = n0 + wn * 32 + j * 8 + qc;
            #pragma unroll
            for (int rr = 0; rr < 2; rr++) {     // row, row+8
                int m = r + rr * 8;
                int b = m / 36, sidx = m - b * 36;
                float* op = out + (size_t)b * FLAT + sidx;
                op[(c + 0) * 36] = acc[i][j][rr * 2 + 0] + bias[c + 0];
                op[(c + 1) * 36] = acc[i][j][rr * 2 + 1] + bias[c + 1];
            }
        }
    }
}

// ---------------- Squash u ----------------
__global__ void squash_u_kernel(const float* __restrict__ c2, float* __restrict__ u) {
    int i = blockIdx.x * 256 + threadIdx.x;
    if (i >= BATCH * ROUTES) return;
    const float4* p = reinterpret_cast<const float4*>(c2 + (size_t)i * 8);
    float4 a = p[0], b = p[1];
    float sn = a.x*a.x + a.y*a.y + a.z*a.z + a.w*a.w
             + b.x*b.x + b.y*b.y + b.z*b.z + b.w*b.w + 1e-7f;
    float sc = sqrtf(sn) / (1.f + sn);
    float4 oa = make_float4(a.x*sc, a.y*sc, a.z*sc, a.w*sc);
    float4 ob = make_float4(b.x*sc, b.y*sc, b.z*sc, b.w*sc);
    float4* q = reinterpret_cast<float4*>(u + (size_t)i * 8);
    q[0] = oa; q[1] = ob;
}

// ---------------- u_hat ----------------
__global__ void uhat_kernel(const float* __restrict__ W, const float* __restrict__ u,
                            float* __restrict__ uhat) {
    __shared__ float Wsm[1280];
    __shared__ float usm[256];
    int r = blockIdx.x;
    int bg = blockIdx.y;
    for (int i = threadIdx.x; i < 1280; i += 256) Wsm[i] = W[(size_t)r * 1280 + i];
    {
        int i = threadIdx.x;
        int bb = bg * 32 + (i >> 3);
        usm[i] = u[(size_t)bb * FLAT + r * 8 + (i & 7)];
    }
    __syncthreads();
    for (int i = threadIdx.x; i < 5120; i += 256) {
        int bi = i / 160, ko = i - bi * 160;
        const float* wp = &Wsm[ko * 8];
        const float* up = &usm[bi * 8];
        float acc = 0.f;
        #pragma unroll
        for (int c = 0; c < 8; c++) acc += wp[c] * up[c];
        uhat[((size_t)(bg * 32 + bi) * ROUTES + r) * 160 + ko] = acc;
    }
}

// ---------------- Routing ----------------
__global__ void zero_bij_kernel(float* __restrict__ bij) {
    int i = blockIdx.x * 256 + threadIdx.x;
    if (i < ROUTES * NCAPS) bij[i] = 0.f;
}

__global__ void softmax_routes_kernel(const float* __restrict__ b, float* __restrict__ c) {
    int k = blockIdx.x;
    __shared__ float red[256];
    int tid = threadIdx.x;
    float m = -1e30f;
    for (int r = tid; r < ROUTES; r += 256) m = fmaxf(m, b[r * 10 + k]);
    red[tid] = m; __syncthreads();
    for (int s = 128; s > 0; s >>= 1) {
        if (tid < s) red[tid] = fmaxf(red[tid], red[tid + s]);
        __syncthreads();
    }
    m = red[0]; __syncthreads();
    float sum = 0.f;
    for (int r = tid; r < ROUTES; r += 256) sum += expf(b[r * 10 + k] - m);
    red[tid] = sum; __syncthreads();
    for (int s = 128; s > 0; s >>= 1) {
        if (tid < s) red[tid] += red[tid + s];
        __syncthreads();
    }
    float inv = 1.f / red[0];
    for (int r = tid; r < ROUTES; r += 256) c[r * 10 + k] = expf(b[r * 10 + k] - m) * inv;
}

__global__ void sv_kernel(const float* __restrict__ cij, const float* __restrict__ uhat,
                          float* __restrict__ v) {
    int b = blockIdx.x, k = blockIdx.y;
    int tid = threadIdx.x;
    float acc[16];
    #pragma unroll
    for (int o = 0; o < 16; o++) acc[o] = 0.f;
    for (int r = tid; r < ROUTES; r += 128) {
        float cc = cij[r * 10 + k];
        const float4* p = reinterpret_cast<const float4*>(uhat + ((size_t)(b * ROUTES + r) * 10 + k) * 16);
        float4 x0 = p[0], x1 = p[1], x2 = p[2], x3 = p[3];
        acc[0]  += cc * x0.x; acc[1]  += cc * x0.y; acc[2]  += cc * x0.z; acc[3]  += cc * x0.w;
        acc[4]  += cc * x1.x; acc[5]  += cc * x1.y; acc[6]  += cc * x1.z; acc[7]  += cc * x1.w;
        acc[8]  += cc * x2.x; acc[9]  += cc * x2.y; acc[10] += cc * x2.z; acc[11] += cc * x2.w;
        acc[12] += cc * x3.x; acc[13] += cc * x3.y; acc[14] += cc * x3.z; acc[15] += cc * x3.w;
    }
    __shared__ float red[128 * 16];
    #pragma unroll
    for (int o = 0; o < 16; o++) red[tid * 16 + o] = acc[o];
    __syncthreads();
    for (int s = 64; s > 0; s >>= 1) {
        if (tid < s) {
            #pragma unroll
            for (int o = 0; o < 16; o++) red[tid * 16 + o] += red[(tid + s) * 16 + o];
        }
        __syncthreads();
    }
    if (tid == 0) {
        float sn = 0.f;
        #pragma unroll
        for (int o = 0; o < 16; o++) sn += red[o] * red[o];
        float sc = sqrtf(sn) / (1.f + sn);
        #pragma unroll
        for (int o = 0; o < 16; o++) v[(b * 10 + k) * 16 + o] = red[o] * sc;
    }
}

__global__ void agree_kernel(const float* __restrict__ uhat, const float* __restrict__ v,
                             float* __restrict__ bij) {
    int r = blockIdx.x, k = blockIdx.y;
    int tid = threadIdx.x;
    __shared__ __align__(16) float vsm[BATCH * 16];
    __shared__ float red[256];
    for (int i = tid; i < BATCH * 16; i += 256) {
        int bb = i >> 4, o = i & 15;
        vsm[i] = v[(bb * 10 + k) * 16 + o];
    }
    __syncthreads();
    float acc = 0.f;
    for (int bb = tid; bb < BATCH; bb += 256) {
        const float4* p = reinterpret_cast<const float4*>(uhat + ((size_t)(bb * ROUTES + r) * 10 + k) * 16);
        const float4* q = reinterpret_cast<const float4*>(&vsm[bb * 16]);
        float4 a0 = p[0], a1 = p[1], a2 = p[2], a3 = p[3];
        float4 b0 = q[0], b1 = q[1], b2 = q[2], b3 = q[3];
        acc += a0.x*b0.x + a0.y*b0.y + a0.z*b0.z + a0.w*b0.w;
        acc += a1.x*b1.x + a1.y*b1.y + a1.z*b1.z + a1.w*b1.w;
        acc += a2.x*b2.x + a2.y*b2.y + a2.z*b2.z + a2.w*b2.w;
        acc += a3.x*b3.x + a3.y*b3.y + a3.z*b3.z + a3.w*b3.w;
    }
    red[tid] = acc; __syncthreads();
    for (int s = 128; s > 0; s >>= 1) {
        if (tid < s) red[tid] += red[tid + s];
        __syncthreads();
    }
    if (tid == 0) bij[r * 10 + k] += red[0] * (1.f / (float)BATCH);
}

// ---------------- Mask / argmax ----------------
__global__ void mask_kernel(const float* __restrict__ v, float* __restrict__ out_obj,
                            float* __restrict__ out_mask, int* __restrict__ best) {
    int b = blockIdx.x * blockDim.x + threadIdx.x;
    if (b >= BATCH) return;
    const float* vb = v + b * 160;
    float bestn = -1.f; int bi = 0;
    #pragma unroll
    for (int k = 0; k < 10; k++) {
        float sn = 0.f;
        #pragma unroll
        for (int o = 0; o < 16; o++) { float t = vb[k * 16 + o]; sn += t * t; }
        if (sn > bestn) { bestn = sn; bi = k; }
    }
    best[b] = bi;
    for (int i = 0; i < 160; i++) out_obj[b * 160 + i] = vb[i];
    #pragma unroll
    for (int k = 0; k < 10; k++) out_mask[b * 10 + k] = (k == bi) ? 1.f : 0.f;
}

// ---------------- Decoder ----------------
__global__ void dec1_kernel(const float* __restrict__ v, const int* __restrict__ best,
                            const float* __restrict__ w1, const float* __restrict__ b1,
                            float* __restrict__ h1) {
    int b = blockIdx.x;
    int j = threadIdx.x;
    __shared__ float vs[16];
    int bi = best[b];
    if (threadIdx.x < 16) vs[threadIdx.x] = v[b * 160 + bi * 16 + threadIdx.x];
    __syncthreads();
    float acc = b1[j];
    #pragma unroll
    for (int o = 0; o < 16; o++) acc += vs[o] * w1[(bi * 16 + o) * 512 + j];
    h1[b * 512 + j] = fmaxf(acc, 0.f);
}

template<int ACT>
__global__ void gemm_act_kernel(const float* __restrict__ A, const float* __restrict__ W,
                                const float* __restrict__ bias, float* __restrict__ C,
                                int M, int N, int K) {
    __shared__ float As[16][64];
    __shared__ float Bs[16][64];
    int tid = threadIdx.x;
    int m0 = blockIdx.y * 64, n0 = blockIdx.x * 64;
    int ty = tid >> 4, tx = tid & 15;
    float acc[4][4];
    #pragma unroll
    for (int i = 0; i < 4; i++)
        #pragma unroll
        for (int j = 0; j < 4; j++) acc[i][j] = 0.f;

    int lam = tid >> 2;
    int lak = (tid & 3) * 4;
    int lbk = tid >> 4;
    int lbn = (tid & 15) * 4;

    for (int k0 = 0; k0 < K; k0 += 16) {
        float4 av = *reinterpret_cast<const float4*>(A + (size_t)(m0 + lam) * K + k0 + lak);
        As[lak + 0][lam] = av.x; As[lak + 1][lam] = av.y;
        As[lak + 2][lam] = av.z; As[lak + 3][lam] = av.w;
        #pragma unroll
        for (int i = 0; i < 4; i++) {
            int n = n0 + lbn + i;
            Bs[lbk][lbn + i] = (n < N) ? W[(size_t)(k0 + lbk) * N + n] : 0.f;
        }
        __syncthreads();
        #pragma unroll
        for (int kk = 0; kk < 16; kk++) {
            float af[4], bf[4];
            #pragma unroll
            for (int i = 0; i < 4; i++) af[i] = As[kk][ty * 4 + i];
            #pragma unroll
            for (int j = 0; j < 4; j++) bf[j] = Bs[kk][tx * 4 + j];
            #pragma unroll
            for (int i = 0; i < 4; i++)
                #pragma unroll
                for (int j = 0; j < 4; j++)
                    acc[i][j] += af[i] * bf[j];
        }
        __syncthreads();
    }
    #pragma unroll
    for (int i = 0; i < 4; i++) {
        int m = m0 + ty * 4 + i;
        #pragma unroll
        for (int j = 0; j < 4; j++) {
            int n = n0 + tx * 4 + j;
            if (n < N) {
                float x = acc[i][j] + bias[n];
                if (ACT == 0) x = fmaxf(x, 0.f);
                else          x = 1.f / (1.f + expf(-x));
                C[(size_t)m * N + n] = x;
            }
        }
    }
}

// ---------------- Host launcher ----------------
extern "C" void kernel_launch(void* const* d_in, const int* in_sizes, int n_in,
                              void* d_out, int out_size) {
    const float* image  = (const float*)d_in[0];
    const float* conv_w = (const float*)d_in[1];
    const float* conv_b = (const float*)d_in[2];
    const float* pc_w   = (const float*)d_in[3];
    const float* pc_b   = (const float*)d_in[4];
    const float* W_obj  = (const float*)d_in[5];
    const float* dec_w1 = (const float*)d_in[6];
    const float* dec_b1 = (const float*)d_in[7];
    const float* dec_w2 = (const float*)d_in[8];
    const float* dec_b2 = (const float*)d_in[9];
    const float* dec_w3 = (const float*)d_in[10];
    const float* dec_b3 = (const float*)d_in[11];

    float* out = (float*)d_out;
    float* out_obj  = out;
    float* out_rec  = out + BATCH * 160;
    float* out_mask = out + BATCH * (160 + 784);

    float* x1   = nullptr; cudaGetSymbolAddress((void**)&x1,   g_x1);
    float* c2   = nullptr; cudaGetSymbolAddress((void**)&c2,   g_c2);
    float* u    = nullptr; cudaGetSymbolAddress((void**)&u,    g_u);
    float* uhat = nullptr; cudaGetSymbolAddress((void**)&uhat, g_uhat);
    float* bij  = nullptr; cudaGetSymbolAddress((void**)&bij,  g_bij);
    float* cij  = nullptr; cudaGetSymbolAddress((void**)&cij,  g_cij);
    float* v    = nullptr; cudaGetSymbolAddress((void**)&v,    g_v);
    int*   best = nullptr; cudaGetSymbolAddress((void**)&best, g_best);
    float* h1   = nullptr; cudaGetSymbolAddress((void**)&h1,   g_h1);
    float* h2   = nullptr; cudaGetSymbolAddress((void**)&h2,   g_h2);

    // 1) conv1 + relu
    conv1_kernel<<<dim3(BATCH, 8), 256>>>(image, conv_w, conv_b, x1);
    // 2) conv2 as split-bf16 tensor-core implicit GEMM (B read directly from pc_w)
    conv2_mma_kernel<<<dim3(N2 / 128, M2 / 128), 256>>>(x1, pc_w, pc_b, c2);
    // 3) squash -> u
    squash_u_kernel<<<(BATCH * ROUTES + 255) / 256, 256>>>(c2, u);
    // 4) u_hat
    uhat_kernel<<<dim3(ROUTES, BATCH / 32), 256>>>(W_obj, u, uhat);
    // 5) routing (3 iterations)
    zero_bij_kernel<<<(ROUTES * NCAPS + 255) / 256, 256>>>(bij);
    for (int it = 0; it < 3; it++) {
        softmax_routes_kernel<<<NCAPS, 256>>>(bij, cij);
        sv_kernel<<<dim3(BATCH, NCAPS), 128>>>(cij, uhat, v);
        if (it < 2)
            agree_kernel<<<dim3(ROUTES, NCAPS), 256>>>(uhat, v, bij);
    }
    // 6) mask + obj output
    mask_kernel<<<2, 256>>>(v, out_obj, out_mask, best);
    // 7) decoder
    dec1_kernel<<<BATCH, 512>>>(v, best, dec_w1, dec_b1, h1);
    gemm_act_kernel<0><<<dim3(1024 / 64, BATCH / 64), 256>>>(h1, dec_w2, dec_b2, h2, BATCH, 1024, 512);
    gemm_act_kernel<1><<<dim3((784 + 63) / 64, BATCH / 64), 256>>>(h2, dec_w3, dec_b3, out_rec, BATCH, 784, 1024);
}